// round 8
// baseline (speedup 1.0000x reference)
#include <cuda_runtime.h>
#include <cstdint>
#include <cstddef>

typedef unsigned long long ull;
#define DINLINE __device__ __forceinline__

namespace {
constexpr int Tlen = 512, OUTW = 24;
constexpr int CL = 8, Br = 16, NTHR = 128;
constexpr int H1S = 260, H2S = 130, XSS = 68;

constexpr int OFF_R1 = 8;                    // [256][96] gate-interleaved
constexpr int OFF_K1 = OFF_R1 + 24576;       // [64][96]
constexpr int OFF_K2 = OFF_K1 + 6144;        // [256][48]
constexpr int OFF_R2 = OFF_K2 + 12288;       // [128][48]
constexpr int OFF_H1 = OFF_R2 + 6144;        // [16][260]
constexpr int OFF_H2 = OFF_H1 + Br * H1S;    // [16][130]
constexpr int OFF_XS = OFF_H2 + Br * H2S;    // [16][68]
constexpr int SMEM_FLOATS = OFF_XS + Br * XSS;          // 56488
constexpr size_t SMEM_BYTES = SMEM_FLOATS * sizeof(float);  // 225952
}

DINLINE float sigf(float v) { return __fdividef(1.0f, 1.0f + __expf(-v)); }
DINLINE float tanh_fast(float v) {
    float e = __expf(2.0f * fabsf(v));
    return copysignf(1.0f - __fdividef(2.0f, e + 1.0f), v);
}
DINLINE void cl_sync() {
    asm volatile("barrier.cluster.arrive.aligned;" ::: "memory");
    asm volatile("barrier.cluster.wait.aligned;" ::: "memory");
}
DINLINE uint32_t mapa_u32(uint32_t a, uint32_t r) {
    uint32_t p; asm("mapa.shared::cluster.u32 %0, %1, %2;" : "=r"(p) : "r"(a), "r"(r));
    return p;
}
DINLINE void st_rem64(uint32_t a, ull v) {
    asm volatile("st.shared::cluster.b64 [%0], %1;" :: "r"(a), "l"(v) : "memory");
}
DINLINE ull pk2(float a, float b) {
    ull r; asm("mov.b64 %0, {%1, %2};" : "=l"(r) : "f"(a), "f"(b)); return r;
}
DINLINE float2 upk(ull v) {
    float2 r; asm("mov.b64 {%0, %1}, %2;" : "=f"(r.x), "=f"(r.y) : "l"(v)); return r;
}
DINLINE void f2(ull& d, ull a, ull b) {
    asm("fma.rn.f32x2 %0, %1, %2, %0;" : "+l"(d) : "l"(a), "l"(b));
}
DINLINE void mb_init(uint32_t a, uint32_t n) {
    asm volatile("mbarrier.init.shared.b64 [%0], %1;" :: "r"(a), "r"(n) : "memory");
}
DINLINE void mb_arrive_rel(uint32_t laddr, uint32_t rank) {
    asm volatile("{ .reg .b32 ra;\n\t"
        "mapa.shared::cluster.u32 ra, %0, %1;\n\t"
        "mbarrier.arrive.release.cluster.shared::cluster.b64 _, [ra]; }"
        :: "r"(laddr), "r"(rank) : "memory");
}
DINLINE void mb_wait(uint32_t a, uint32_t par) {
    asm volatile("{ .reg .pred P;\n"
        "W%=:\n\t"
        "mbarrier.try_wait.parity.acquire.cluster.shared::cta.b64 P, [%0], %1, 0x989680;\n\t"
        "@P bra.uni D%=;\n\t"
        "bra.uni W%=;\n"
        "D%=: }" :: "r"(a), "r"(par) : "memory");
}

__global__ void __launch_bounds__(NTHR, 1) __cluster_dims__(CL, 1, 1)
gru_stack_kernel(const float* __restrict__ x,  const float* __restrict__ k1,
                 const float* __restrict__ r1, const float* __restrict__ b1,
                 const float* __restrict__ k2, const float* __restrict__ r2,
                 const float* __restrict__ b2, const float* __restrict__ w3,
                 const float* __restrict__ b3, const float* __restrict__ w4,
                 const float* __restrict__ b4, const float* __restrict__ w5,
                 const float* __restrict__ b5, float* __restrict__ out)
{
    extern __shared__ float sm[];
    const int tid = threadIdx.x;
    const int c = blockIdx.x & (CL - 1);
    const int g = blockIdx.x >> 3;
    const int row = tid >> 3, ct = tid & 7;

    uint32_t smem_base;
    asm("{ .reg .u64 t; cvta.to.shared.u64 t, %1; cvt.u32.u64 %0, t; }"
        : "=r"(smem_base) : "l"(sm));
    const uint32_t mbFREE = smem_base, mbRDY1 = smem_base + 8, mbRDY2 = smem_base + 16;
    if (tid == 0) { mb_init(mbFREE, 8); mb_init(mbRDY1, 8); mb_init(mbRDY2, 8); }

    // ---- Stage weights, gate-interleaved: row k = 8 groups x [4z|4r|4h] ----
    for (int idx = tid; idx < 24576; idx += NTHR) {
        int k = idx / 96, j = idx % 96, gg = j / 12, q = j % 12;
        sm[OFF_R1 + idx] = r1[k * 768 + (q >> 2) * 256 + (c << 5) + (gg << 2) + (q & 3)];
    }
    for (int idx = tid; idx < 6144; idx += NTHR) {
        int k = idx / 96, j = idx % 96, gg = j / 12, q = j % 12;
        sm[OFF_K1 + idx] = k1[k * 768 + (q >> 2) * 256 + (c << 5) + (gg << 2) + (q & 3)];
    }
    for (int idx = tid; idx < 12288; idx += NTHR) {   // K2: 8 groups x [2z|2r|2h]
        int k = idx / 48, j = idx % 48, gg = j / 6, q = j % 6;
        sm[OFF_K2 + idx] = k2[k * 384 + (q >> 1) * 128 + (c << 4) + (gg << 1) + (q & 1)];
    }
    for (int idx = tid; idx < 6144; idx += NTHR) {
        int k = idx / 48, j = idx % 48, gg = j / 6, q = j % 6;
        sm[OFF_R2 + idx] = r2[k * 384 + (q >> 1) * 128 + (c << 4) + (gg << 1) + (q & 1)];
    }
    for (int idx = tid; idx < Br * H1S; idx += NTHR) sm[OFF_H1 + idx] = 0.0f;
    for (int idx = tid; idx < Br * H2S; idx += NTHR) sm[OFF_H2 + idx] = 0.0f;
    #pragma unroll
    for (int j = 0; j < 2; j++) {   // x(0)
        int i = tid * 2 + j, r = i >> 4, f4 = i & 15;
        *(float4*)(sm + OFF_XS + r * XSS + f4 * 4) =
            *(const float4*)(x + ((size_t)(g * Br + r) * Tlen) * 64 + f4 * 4);
    }

    // ---- biases (registers) ----
    ull Bz0, Bz1, Br0, Br1, Bx0, Bx1, Bh0, Bh1;
    {
        int u = (c << 5) + ct * 4;
        Bz0 = pk2(b1[u] + b1[768 + u],     b1[u+1] + b1[769 + u]);
        Bz1 = pk2(b1[u+2] + b1[770 + u],   b1[u+3] + b1[771 + u]);
        Br0 = pk2(b1[256+u] + b1[1024+u],  b1[257+u] + b1[1025+u]);
        Br1 = pk2(b1[258+u] + b1[1026+u],  b1[259+u] + b1[1027+u]);
        Bx0 = pk2(b1[512+u], b1[513+u]);   Bx1 = pk2(b1[514+u], b1[515+u]);
        Bh0 = pk2(b1[1280+u], b1[1281+u]); Bh1 = pk2(b1[1282+u], b1[1283+u]);
    }
    ull Cz, Cr, Cx, Ch;
    {
        int u = (c << 4) + ct * 2;
        Cz = pk2(b2[u] + b2[384+u],       b2[u+1] + b2[385+u]);
        Cr = pk2(b2[128+u] + b2[512+u],   b2[129+u] + b2[513+u]);
        Cx = pk2(b2[256+u], b2[257+u]);
        Ch = pk2(b2[640+u], b2[641+u]);
    }

    // ---- precomputed remote addresses ----
    const uint32_t h1la = smem_base + (uint32_t)(OFF_H1 + row * H1S + (c << 5) + ct * 4) * 4u;
    const uint32_t h2la = smem_base + (uint32_t)(OFF_H2 + row * H2S + (c << 4) + ct * 2) * 4u;
    uint32_t map1[CL], map2[CL];
    #pragma unroll
    for (int rk = 0; rk < CL; rk++) { map1[rk] = mapa_u32(h1la, rk); map2[rk] = mapa_u32(h2la, rk); }

    const ull* Wr1 = (const ull*)(sm + OFF_R1);
    const ull* Wk1 = (const ull*)(sm + OFF_K1);
    const ull* Wk2 = (const ull*)(sm + OFF_K2);
    const ull* Wr2 = (const ull*)(sm + OFF_R2);
    const float* h1row = sm + OFF_H1 + row * H1S;
    const float* h2row = sm + OFF_H2 + row * H2S;
    const float* xrow  = sm + OFF_XS + row * XSS;

    float hp[4] = {0, 0, 0, 0};
    float hq[2] = {0, 0};

    __syncthreads();
    cl_sync();   // inits + weights visible cluster-wide

    for (int t = 0; t < Tlen; t++) {
        const uint32_t par = (uint32_t)(t & 1);
        float4 xr0, xr1;
        if (t + 1 < Tlen) {
            int i0 = tid * 2, r0 = i0 >> 4, f0 = i0 & 15;
            xr0 = *(const float4*)(x + ((size_t)(g * Br + r0) * Tlen + t + 1) * 64 + f0 * 4);
            int i1 = i0 + 1, r1i = i1 >> 4, f1 = i1 & 15;
            xr1 = *(const float4*)(x + ((size_t)(g * Br + r1i) * Tlen + t + 1) * 64 + f1 * 4);
        }

        // ---- GRU1: full projections for 4 owned units ----
        ull az0 = Bz0, az1 = Bz1, ar0 = Br0, ar1 = Br1;
        ull ax0 = Bx0, ax1 = Bx1, ah0 = Bh0, ah1 = Bh1;
        #pragma unroll 4
        for (int k = 0; k < 64; k++) {       // x @ k1
            ull v = pk2(xrow[k], xrow[k]);
            const ull* p = Wk1 + k * 48 + ct * 6;
            ulonglong2 wz = *(const ulonglong2*)(p);
            ulonglong2 wr = *(const ulonglong2*)(p + 2);
            ulonglong2 wh = *(const ulonglong2*)(p + 4);
            f2(az0, v, wz.x); f2(az1, v, wz.y);
            f2(ar0, v, wr.x); f2(ar1, v, wr.y);
            f2(ax0, v, wh.x); f2(ax1, v, wh.y);
        }
        #pragma unroll 4
        for (int k = 0; k < 256; k++) {      // h1(t-1) @ r1
            ull v = pk2(h1row[k], h1row[k]);
            const ull* p = Wr1 + k * 48 + ct * 6;
            ulonglong2 wz = *(const ulonglong2*)(p);
            ulonglong2 wr = *(const ulonglong2*)(p + 2);
            ulonglong2 wh = *(const ulonglong2*)(p + 4);
            f2(az0, v, wz.x); f2(az1, v, wz.y);
            f2(ar0, v, wr.x); f2(ar1, v, wr.y);
            f2(ah0, v, wh.x); f2(ah1, v, wh.y);
        }

        // ---- GRU2 recurrent projection (h2(t-1) @ r2) ----
        if (t > 0) mb_wait(mbRDY2, (uint32_t)((t - 1) & 1));
        ull cz = Cz, cr = Cr, cx = Cx, ch = Ch;
        #pragma unroll 4
        for (int k = 0; k < 128; k++) {
            ull v = pk2(h2row[k], h2row[k]);
            const ull* p = Wr2 + k * 24 + ct * 3;
            f2(cz, v, p[0]); f2(cr, v, p[1]); f2(ch, v, p[2]);
        }
        __syncthreads();                     // S1: all reads of h1(t-1), h2(t-1), x(t) done
        if (tid < 8) mb_arrive_rel(mbFREE, (uint32_t)tid);
        if (t + 1 < Tlen) {
            int i0 = tid * 2, r0 = i0 >> 4, f0 = i0 & 15;
            *(float4*)(sm + OFF_XS + r0 * XSS + f0 * 4) = xr0;
            int i1 = i0 + 1, r1i = i1 >> 4, f1 = i1 & 15;
            *(float4*)(sm + OFF_XS + r1i * XSS + f1 * 4) = xr1;
        }

        // ---- GRU1 gates (all local) ----
        {
            float2 vz0 = upk(az0), vz1 = upk(az1), vr0 = upk(ar0), vr1 = upk(ar1);
            float2 vx0 = upk(ax0), vx1 = upk(ax1), vh0 = upk(ah0), vh1 = upk(ah1);
            float zz[4] = {sigf(vz0.x), sigf(vz0.y), sigf(vz1.x), sigf(vz1.y)};
            float rr[4] = {sigf(vr0.x), sigf(vr0.y), sigf(vr1.x), sigf(vr1.y)};
            float xx[4] = {vx0.x, vx0.y, vx1.x, vx1.y};
            float hh[4] = {vh0.x, vh0.y, vh1.x, vh1.y};
            #pragma unroll
            for (int i = 0; i < 4; i++) {
                float cand = tanh_fast(xx[i] + rr[i] * hh[i]);
                hp[i] = zz[i] * hp[i] + (1.0f - zz[i]) * cand;
            }
        }
        mb_wait(mbFREE, par);                // WAR cluster-wide
        {
            ull q0 = pk2(hp[0], hp[1]), q1 = pk2(hp[2], hp[3]);
            #pragma unroll
            for (int rk = 0; rk < CL; rk++) { st_rem64(map1[rk], q0); st_rem64(map1[rk] + 8, q1); }
        }
        __syncthreads();                     // S2: all h1 stores issued
        if (tid < 8) mb_arrive_rel(mbRDY1, (uint32_t)tid);
        mb_wait(mbRDY1, par);                // h1(t) visible locally

        // ---- GRU2 input projection (h1(t) @ k2) ----
        #pragma unroll 4
        for (int k = 0; k < 256; k++) {
            ull v = pk2(h1row[k], h1row[k]);
            const ull* p = Wk2 + k * 24 + ct * 3;
            f2(cz, v, p[0]); f2(cr, v, p[1]); f2(cx, v, p[2]);
        }
        // ---- GRU2 gates + publish ----
        {
            float2 vz = upk(cz), vr = upk(cr), vx = upk(cx), vh = upk(ch);
            float z0 = sigf(vz.x), r0 = sigf(vr.x);
            float z1 = sigf(vz.y), r1g = sigf(vr.y);
            hq[0] = z0 * hq[0] + (1.0f - z0) * tanh_fast(vx.x + r0 * vh.x);
            hq[1] = z1 * hq[1] + (1.0f - z1) * tanh_fast(vx.y + r1g * vh.y);
            ull q = pk2(hq[0], hq[1]);
            #pragma unroll
            for (int rk = 0; rk < CL; rk++) st_rem64(map2[rk], q);
        }
        __syncthreads();                     // S3: all h2 stores issued
        if (tid < 8) mb_arrive_rel(mbRDY2, (uint32_t)tid);
    }
    mb_wait(mbRDY2, (uint32_t)((Tlen - 1) & 1));   // final h2 delivered everywhere

    // ---- Dense head (rank 0 CTAs) ----
    if (c == 0) {
        float* sD3 = sm + OFF_XS;            // [16][64] (x buffer dead)
        float* sD4 = sm + OFF_H1;            // [16][32] (h1 dead)
        __syncthreads();
        for (int idx = tid; idx < Br * 64; idx += NTHR) {
            int r = idx >> 6, o = idx & 63;
            float a = b3[o];
            #pragma unroll 8
            for (int k = 0; k < 128; k++) a += sm[OFF_H2 + r * H2S + k] * w3[k * 64 + o];
            sD3[idx] = a;
        }
        __syncthreads();
        for (int idx = tid; idx < Br * 32; idx += NTHR) {
            int r = idx >> 5, o = idx & 31;
            float a = b4[o];
            #pragma unroll 8
            for (int k = 0; k < 64; k++) a += sD3[r * 64 + k] * w4[k * 32 + o];
            sD4[idx] = a;
        }
        __syncthreads();
        for (int idx = tid; idx < Br * OUTW; idx += NTHR) {
            int r = idx / OUTW, o = idx % OUTW;
            float a = b5[o];
            #pragma unroll 8
            for (int k = 0; k < 32; k++) a += sD4[r * 32 + k] * w5[k * OUTW + o];
            out[(g * Br + r) * OUTW + o] = a;
        }
    }
}

extern "C" void kernel_launch(void* const* d_in, const int* in_sizes, int n_in,
                              void* d_out, int out_size) {
    (void)in_sizes; (void)n_in; (void)out_size;
    const float* x  = (const float*)d_in[0];
    const float* k1 = (const float*)d_in[1];
    const float* r1 = (const float*)d_in[2];
    const float* b1 = (const float*)d_in[3];
    const float* k2 = (const float*)d_in[4];
    const float* r2 = (const float*)d_in[5];
    const float* b2 = (const float*)d_in[6];
    const float* w3 = (const float*)d_in[7];
    const float* b3 = (const float*)d_in[8];
    const float* w4 = (const float*)d_in[9];
    const float* b4 = (const float*)d_in[10];
    const float* w5 = (const float*)d_in[11];
    const float* b5 = (const float*)d_in[12];
    float* out = (float*)d_out;

    cudaFuncSetAttribute(gru_stack_kernel,
                         cudaFuncAttributeMaxDynamicSharedMemorySize, (int)SMEM_BYTES);
    gru_stack_kernel<<<128, NTHR, SMEM_BYTES>>>(
        x, k1, r1, b1, k2, r2, b2, w3, b3, w4, b4, w5, b5, out);
}

// round 10
// speedup vs baseline: 1.1551x; 1.1551x over previous
#include <cuda_runtime.h>
#include <cstdint>
#include <cstddef>
typedef unsigned long long ull; typedef ulonglong2 ull2;
#define DI __device__ __forceinline__

namespace {
constexpr int T = 512, OUTW = 24, CL = 8, Br = 16, NTHR = 256;
constexpr int H1S = 258, H2S = 130, XSS = 68;   // EVEN strides: b64-aligned h rows
constexpr int OFF_R1 = 16;                  // [256][96] gate-interleaved
constexpr int OFF_K1 = OFF_R1 + 24576;      // [64][96]
constexpr int OFF_K2 = OFF_K1 + 6144;       // [256][48]
constexpr int OFF_R2 = OFF_K2 + 12288;      // [128][48]
constexpr int OFF_H1 = OFF_R2 + 6144;       // [16][258]
constexpr int OFF_H2 = OFF_H1 + Br * H1S;   // [16][130]
constexpr int OFF_XS = OFF_H2 + Br * H2S;   // [2][16][68]
constexpr int SMEM_FLOATS = OFF_XS + 2 * Br * XSS;          // 57552
constexpr size_t SMEM_BYTES = SMEM_FLOATS * sizeof(float);  // 230208
}

DI float sigf(float v) { return __fdividef(1.f, 1.f + __expf(-v)); }
DI float tanhf_(float v) {
    float e = __expf(2.f * fabsf(v));
    return copysignf(1.f - __fdividef(2.f, e + 1.f), v);
}
DI float gate1(float z, float r, float xx, float hh, float hp) {
    float zs = sigf(z), rs = sigf(r);
    return zs * hp + (1.f - zs) * tanhf_(xx + rs * hh);
}
DI void cl_sync() {
    asm volatile("barrier.cluster.arrive.aligned;" ::: "memory");
    asm volatile("barrier.cluster.wait.aligned;" ::: "memory");
}
DI uint32_t mapa_u32(uint32_t a, uint32_t r) {
    uint32_t p; asm("mapa.shared::cluster.u32 %0,%1,%2;" : "=r"(p) : "r"(a), "r"(r)); return p;
}
DI void st_rem64(uint32_t a, ull v) {
    asm volatile("st.shared::cluster.b64 [%0],%1;" :: "r"(a), "l"(v) : "memory");
}
DI ull pk2(float a, float b) { ull r; asm("mov.b64 %0,{%1,%2};" : "=l"(r) : "f"(a), "f"(b)); return r; }
DI float2 upk(ull v) { float2 r; asm("mov.b64 {%0,%1},%2;" : "=f"(r.x), "=f"(r.y) : "l"(v)); return r; }
DI void f2(ull& d, ull a, ull b) { asm("fma.rn.f32x2 %0,%1,%2,%0;" : "+l"(d) : "l"(a), "l"(b)); }
DI void mb_init(uint32_t a, uint32_t n) {
    asm volatile("mbarrier.init.shared.b64 [%0],%1;" :: "r"(a), "r"(n) : "memory");
}
DI void mb_post(uint32_t la, uint32_t rk) {
    asm volatile("{ .reg .b32 ra;\n\t"
        "mapa.shared::cluster.u32 ra,%0,%1;\n\t"
        "mbarrier.arrive.release.cluster.shared::cluster.b64 _,[ra]; }"
        :: "r"(la), "r"(rk) : "memory");
}
DI void mb_wait(uint32_t a, uint32_t p) {
    asm volatile("{ .reg .pred P;\n"
        "W%=: mbarrier.try_wait.parity.acquire.cluster.shared::cta.b64 P,[%0],%1,0x989680;\n\t"
        "@P bra.uni D%=;\n\t"
        "bra.uni W%=;\n"
        "D%=: }" :: "r"(a), "r"(p) : "memory");
}

__global__ void __launch_bounds__(NTHR, 1) __cluster_dims__(CL, 1, 1)
gru_stack_kernel(const float* __restrict__ x,  const float* __restrict__ k1,
                 const float* __restrict__ r1, const float* __restrict__ b1,
                 const float* __restrict__ k2, const float* __restrict__ r2,
                 const float* __restrict__ b2, const float* __restrict__ w3,
                 const float* __restrict__ b3, const float* __restrict__ w4,
                 const float* __restrict__ b4, const float* __restrict__ w5,
                 const float* __restrict__ b5, float* __restrict__ out)
{
    extern __shared__ float sm[];
    const int tid = threadIdx.x;
    const int c = blockIdx.x & 7, g = blockIdx.x >> 3;

    uint32_t sb;
    asm("{ .reg .u64 t; cvta.to.shared.u64 t,%1; cvt.u32.u64 %0,t; }" : "=r"(sb) : "l"(sm));
    const uint32_t mRDY1 = sb, mRDY2 = sb + 8, mF1a = sb + 16, mF1b = sb + 24, mF2 = sb + 32;
    if (tid == 0) { mb_init(mRDY1,8); mb_init(mRDY2,8); mb_init(mF1a,8); mb_init(mF1b,8); mb_init(mF2,8); }

    // weights: GRU1 gate-interleaved [4z|4r|4h] x 8 groups; GRU2 [2z|2r|2h] x 8
    for (int i = tid; i < 24576; i += NTHR) {
        int k = i / 96, j = i % 96, gg = j / 12, q = j % 12;
        sm[OFF_R1 + i] = r1[k*768 + (q>>2)*256 + (c<<5) + (gg<<2) + (q&3)];
    }
    for (int i = tid; i < 6144; i += NTHR) {
        int k = i / 96, j = i % 96, gg = j / 12, q = j % 12;
        sm[OFF_K1 + i] = k1[k*768 + (q>>2)*256 + (c<<5) + (gg<<2) + (q&3)];
    }
    for (int i = tid; i < 12288; i += NTHR) {
        int k = i / 48, j = i % 48, gg = j / 6, q = j % 6;
        sm[OFF_K2 + i] = k2[k*384 + (q>>1)*128 + (c<<4) + (gg<<1) + (q&1)];
    }
    for (int i = tid; i < 6144; i += NTHR) {
        int k = i / 48, j = i % 48, gg = j / 6, q = j % 6;
        sm[OFF_R2 + i] = r2[k*384 + (q>>1)*128 + (c<<4) + (gg<<1) + (q&1)];
    }
    for (int i = tid; i < Br*H1S; i += NTHR) sm[OFF_H1 + i] = 0.f;
    for (int i = tid; i < Br*H2S; i += NTHR) sm[OFF_H2 + i] = 0.f;
    if (tid < 128) {   // x(0) -> buf0
        #pragma unroll
        for (int j = 0; j < 2; j++) {
            int i = tid*2 + j, r = i >> 4, f = i & 15;
            *(float4*)(sm + OFF_XS + r*XSS + f*4) =
                *(const float4*)(x + ((size_t)(g*Br + r)*T)*64 + f*4);
        }
    }
    __syncthreads();
    cl_sync();

    if (tid < 128) {
        // ================= Team1: GRU1 =================
        const int row = tid >> 3, ct = tid & 7;
        ull Bz0,Bz1,Br0_,Br1_,Bx0,Bx1,Bh0,Bh1;
        {   int u = (c<<5) + ct*4;
            Bz0 = pk2(b1[u]+b1[768+u],       b1[u+1]+b1[769+u]);
            Bz1 = pk2(b1[u+2]+b1[770+u],     b1[u+3]+b1[771+u]);
            Br0_= pk2(b1[256+u]+b1[1024+u],  b1[257+u]+b1[1025+u]);
            Br1_= pk2(b1[258+u]+b1[1026+u],  b1[259+u]+b1[1027+u]);
            Bx0 = pk2(b1[512+u],b1[513+u]);  Bx1 = pk2(b1[514+u],b1[515+u]);
            Bh0 = pk2(b1[1280+u],b1[1281+u]); Bh1 = pk2(b1[1282+u],b1[1283+u]); }
        uint32_t map1[CL];
        {   uint32_t la = sb + (uint32_t)(OFF_H1 + row*H1S + (c<<5) + ct*4)*4u;
            #pragma unroll
            for (int rk = 0; rk < CL; rk++) map1[rk] = mapa_u32(la, rk); }
        const ull* Wk1 = (const ull*)(sm + OFF_K1);
        const ull* Wr1 = (const ull*)(sm + OFF_R1);
        const float* h1row = sm + OFF_H1 + row*H1S;
        float hp[4] = {0,0,0,0};

        for (int t = 0; t < T; t++) {
            if (t) mb_wait(mRDY1, (t-1)&1);
            float4 xr0, xr1;
            if (t+1 < T) {
                int i0 = tid*2, r0 = i0>>4, f0 = i0&15;
                xr0 = *(const float4*)(x + ((size_t)(g*Br+r0)*T + t+1)*64 + f0*4);
                int i1 = i0+1, r1i = i1>>4, f1 = i1&15;
                xr1 = *(const float4*)(x + ((size_t)(g*Br+r1i)*T + t+1)*64 + f1*4);
            }
            ull az0=Bz0,az1=Bz1,ar0=Br0_,ar1=Br1_,ax0=Bx0,ax1=Bx1,ah0=Bh0,ah1=Bh1;
            const float* xrow = sm + OFF_XS + (t&1)*Br*XSS + row*XSS;
            #pragma unroll 4
            for (int k = 0; k < 64; k++) {
                ull v = pk2(xrow[k], xrow[k]);
                const ull* p = Wk1 + k*48 + ct*6;
                ull2 wz = *(const ull2*)p, wr = *(const ull2*)(p+2), wh = *(const ull2*)(p+4);
                f2(az0,v,wz.x); f2(az1,v,wz.y);
                f2(ar0,v,wr.x); f2(ar1,v,wr.y);
                f2(ax0,v,wh.x); f2(ax1,v,wh.y);
            }
            #pragma unroll 4
            for (int k = 0; k < 256; k++) {
                ull v = pk2(h1row[k], h1row[k]);
                const ull* p = Wr1 + k*48 + ct*6;
                ull2 wz = *(const ull2*)p, wr = *(const ull2*)(p+2), wh = *(const ull2*)(p+4);
                f2(az0,v,wz.x); f2(az1,v,wz.y);
                f2(ar0,v,wr.x); f2(ar1,v,wr.y);
                f2(ah0,v,wh.x); f2(ah1,v,wh.y);
            }
            asm volatile("bar.sync 1,128;" ::: "memory");
            if (tid < 8) mb_post(mF1a, (uint32_t)tid);
            if (t+1 < T) {
                int i0 = tid*2, r0 = i0>>4, f0 = i0&15;
                *(float4*)(sm + OFF_XS + ((t+1)&1)*Br*XSS + r0*XSS + f0*4) = xr0;
                int i1 = i0+1, r1i = i1>>4, f1 = i1&15;
                *(float4*)(sm + OFF_XS + ((t+1)&1)*Br*XSS + r1i*XSS + f1*4) = xr1;
            }
            {   float2 z0 = upk(az0), z1 = upk(az1), r0 = upk(ar0), r1v = upk(ar1);
                float2 x0 = upk(ax0), x1 = upk(ax1), h0 = upk(ah0), h1v = upk(ah1);
                hp[0] = gate1(z0.x, r0.x, x0.x, h0.x, hp[0]);
                hp[1] = gate1(z0.y, r0.y, x0.y, h0.y, hp[1]);
                hp[2] = gate1(z1.x, r1v.x, x1.x, h1v.x, hp[2]);
                hp[3] = gate1(z1.y, r1v.y, x1.y, h1v.y, hp[3]); }
            if (t) mb_wait(mF1b, (t-1)&1);      // Team2 everywhere done reading h1(t-1)
            mb_wait(mF1a, t&1);                 // Team1 everywhere done reading h1(t-1)
            {   ull q0 = pk2(hp[0], hp[1]), q1 = pk2(hp[2], hp[3]);
                #pragma unroll
                for (int rk = 0; rk < CL; rk++) { st_rem64(map1[rk], q0); st_rem64(map1[rk]+8, q1); } }
            asm volatile("bar.sync 1,128;" ::: "memory");
            if (tid < 8) mb_post(mRDY1, (uint32_t)tid);
        }
        mb_wait(mRDY1, (T-1)&1);
        mb_wait(mRDY2, (T-1)&1);
    } else {
        // ================= Team2: GRU2 =================
        const int tt = tid - 128, row = tt >> 3, ct = tt & 7;
        ull Cz,Cr,Cx,Ch;
        {   int u = (c<<4) + ct*2;
            Cz = pk2(b2[u]+b2[384+u],     b2[u+1]+b2[385+u]);
            Cr = pk2(b2[128+u]+b2[512+u], b2[129+u]+b2[513+u]);
            Cx = pk2(b2[256+u],b2[257+u]);
            Ch = pk2(b2[640+u],b2[641+u]); }
        uint32_t map2[CL];
        {   uint32_t la = sb + (uint32_t)(OFF_H2 + row*H2S + (c<<4) + ct*2)*4u;
            #pragma unroll
            for (int rk = 0; rk < CL; rk++) map2[rk] = mapa_u32(la, rk); }
        const ull* Wk2 = (const ull*)(sm + OFF_K2);
        const ull* Wr2 = (const ull*)(sm + OFF_R2);
        const float* h1row = sm + OFF_H1 + row*H1S;
        const float* h2row = sm + OFF_H2 + row*H2S;
        float hq[2] = {0,0};

        for (int s = 0; s < T; s++) {
            if (s) mb_wait(mRDY2, (s-1)&1);     // h2(s-1) delivered
            ull cz = Cz, cr = Cr, cx = Cx, ch = Ch;
            #pragma unroll 4
            for (int k = 0; k < 128; k++) {     // h2(s-1) @ r2
                ull v = pk2(h2row[k], h2row[k]);
                const ull* p = Wr2 + k*24 + ct*3;
                f2(cz, v, p[0]); f2(cr, v, p[1]); f2(ch, v, p[2]);
            }
            asm volatile("bar.sync 2,128;" ::: "memory");
            if (tt < 8) mb_post(mF2, (uint32_t)tt);
            mb_wait(mRDY1, s&1);                // h1(s) delivered
            #pragma unroll 4
            for (int k = 0; k < 256; k++) {     // h1(s) @ k2
                ull v = pk2(h1row[k], h1row[k]);
                const ull* p = Wk2 + k*24 + ct*3;
                f2(cz, v, p[0]); f2(cr, v, p[1]); f2(cx, v, p[2]);
            }
            asm volatile("bar.sync 2,128;" ::: "memory");
            if (tt < 8) mb_post(mF1b, (uint32_t)tt);
            {   float2 z = upk(cz), r = upk(cr), xx = upk(cx), hh = upk(ch);
                hq[0] = gate1(z.x, r.x, xx.x, hh.x, hq[0]);
                hq[1] = gate1(z.y, r.y, xx.y, hh.y, hq[1]); }
            mb_wait(mF2, s&1);                  // all CTAs done reading h2(s-1)
            ull q = pk2(hq[0], hq[1]);
            #pragma unroll
            for (int rk = 0; rk < CL; rk++) st_rem64(map2[rk], q);
            asm volatile("bar.sync 2,128;" ::: "memory");
            if (tt < 8) mb_post(mRDY2, (uint32_t)tt);
        }
        mb_wait(mRDY2, (T-1)&1);
    }
    __syncthreads();

    // ---- Dense head (rank 0 CTAs, 256 threads) ----
    if (c == 0) {
        float* sD3 = sm + OFF_XS;           // [16][64]
        float* sD4 = sm + OFF_H1;           // [16][32]
        for (int i = tid; i < Br*64; i += NTHR) {
            int r = i >> 6, o = i & 63;
            float a = b3[o];
            #pragma unroll 8
            for (int k = 0; k < 128; k++) a += sm[OFF_H2 + r*H2S + k] * w3[k*64 + o];
            sD3[i] = a;
        }
        __syncthreads();
        for (int i = tid; i < Br*32; i += NTHR) {
            int r = i >> 5, o = i & 31;
            float a = b4[o];
            #pragma unroll 8
            for (int k = 0; k < 64; k++) a += sD3[r*64 + k] * w4[k*32 + o];
            sD4[i] = a;
        }
        __syncthreads();
        for (int i = tid; i < Br*OUTW; i += NTHR) {
            int r = i / OUTW, o = i % OUTW;
            float a = b5[o];
            #pragma unroll 8
            for (int k = 0; k < 32; k++) a += sD4[r*32 + k] * w5[k*OUTW + o];
            out[(g*Br + r)*OUTW + o] = a;
        }
    }
}

extern "C" void kernel_launch(void* const* d_in, const int* in_sizes, int n_in,
                              void* d_out, int out_size) {
    (void)in_sizes; (void)n_in; (void)out_size;
    const float* x  = (const float*)d_in[0];
    const float* k1 = (const float*)d_in[1];
    const float* r1 = (const float*)d_in[2];
    const float* b1 = (const float*)d_in[3];
    const float* k2 = (const float*)d_in[4];
    const float* r2 = (const float*)d_in[5];
    const float* b2 = (const float*)d_in[6];
    const float* w3 = (const float*)d_in[7];
    const float* b3 = (const float*)d_in[8];
    const float* w4 = (const float*)d_in[9];
    const float* b4 = (const float*)d_in[10];
    const float* w5 = (const float*)d_in[11];
    const float* b5 = (const float*)d_in[12];
    float* out = (float*)d_out;
    cudaFuncSetAttribute(gru_stack_kernel,
                         cudaFuncAttributeMaxDynamicSharedMemorySize, (int)SMEM_BYTES);
    gru_stack_kernel<<<128, NTHR, SMEM_BYTES>>>(
        x, k1, r1, b1, k2, r2, b2, w3, b3, w4, b4, w5, b5, out);
}

// round 11
// speedup vs baseline: 1.2322x; 1.0667x over previous
#include <cuda_runtime.h>
#include <cstdint>
#include <cstddef>
typedef unsigned long long ull; typedef ulonglong2 ull2;
#define DI __device__ __forceinline__

namespace {
constexpr int T = 512, OUTW = 24, CL = 8, Br = 16, NTHR = 128;
constexpr int H1S = 258, H2S = 130, XSS = 68;
constexpr int OFF_R1 = 16;                  // [256][96]  z|r|h col blocks
constexpr int OFF_K2 = OFF_R1 + 24576;      // [256][48]
constexpr int OFF_R2 = OFF_K2 + 12288;      // [128][48]
constexpr int OFF_H1 = OFF_R2 + 6144;       // 2 x [16][258] (double buffer)
constexpr int OFF_H2 = OFF_H1 + 2 * Br * H1S;   // [16][130]
constexpr int OFF_XS = OFF_H2 + Br * H2S;   // [16][68]
constexpr int OFF_SC = OFF_XS + Br * XSS;   // 1536 ull scratch
constexpr int SMEM_FLOATS = OFF_SC + 3072;  // 57520
constexpr size_t SMEM_BYTES = SMEM_FLOATS * sizeof(float);  // 230080
constexpr unsigned H1BUF_B = (unsigned)(Br * H1S * 4);      // 16512 bytes
}

DI float sigf(float v) { return __fdividef(1.f, 1.f + __expf(-v)); }
DI float tanhf_(float v) {
    float e = __expf(2.f * fabsf(v));
    return copysignf(1.f - __fdividef(2.f, e + 1.f), v);
}
DI void cl_sync() {
    asm volatile("barrier.cluster.arrive.aligned;" ::: "memory");
    asm volatile("barrier.cluster.wait.aligned;" ::: "memory");
}
DI uint32_t mapa_u32(uint32_t a, uint32_t r) {
    uint32_t p; asm("mapa.shared::cluster.u32 %0,%1,%2;" : "=r"(p) : "r"(a), "r"(r)); return p;
}
DI void st_rem64(uint32_t a, ull v) {
    asm volatile("st.shared::cluster.b64 [%0],%1;" :: "r"(a), "l"(v) : "memory");
}
DI ull pk2(float a, float b) { ull r; asm("mov.b64 %0,{%1,%2};" : "=l"(r) : "f"(a), "f"(b)); return r; }
DI float2 upk(ull v) { float2 r; asm("mov.b64 {%0,%1},%2;" : "=f"(r.x), "=f"(r.y) : "l"(v)); return r; }
DI void f2(ull& d, ull a, ull b) { asm("fma.rn.f32x2 %0,%1,%2,%0;" : "+l"(d) : "l"(a), "l"(b)); }
DI void a2(ull& d, ull b) { asm("add.rn.f32x2 %0,%0,%1;" : "+l"(d) : "l"(b)); }
DI void mb_init(uint32_t a, uint32_t n) {
    asm volatile("mbarrier.init.shared.b64 [%0],%1;" :: "r"(a), "r"(n) : "memory");
}
DI void mb_post(uint32_t la, uint32_t rk) {
    asm volatile("{ .reg .b32 ra;\n\t"
        "mapa.shared::cluster.u32 ra,%0,%1;\n\t"
        "mbarrier.arrive.release.cluster.shared::cluster.b64 _,[ra]; }"
        :: "r"(la), "r"(rk) : "memory");
}
DI void mb_wait(uint32_t a, uint32_t p) {
    asm volatile("{ .reg .pred P;\n"
        "W%=: mbarrier.try_wait.parity.acquire.cluster.shared::cta.b64 P,[%0],%1,0x989680;\n\t"
        "@P bra.uni D%=;\n\t"
        "bra.uni W%=;\n"
        "D%=: }" :: "r"(a), "r"(p) : "memory");
}

__global__ void __launch_bounds__(NTHR, 1) __cluster_dims__(CL, 1, 1)
gru_stack_kernel(const float* __restrict__ x,  const float* __restrict__ k1,
                 const float* __restrict__ r1, const float* __restrict__ b1,
                 const float* __restrict__ k2, const float* __restrict__ r2,
                 const float* __restrict__ b2, const float* __restrict__ w3,
                 const float* __restrict__ b3, const float* __restrict__ w4,
                 const float* __restrict__ b4, const float* __restrict__ w5,
                 const float* __restrict__ b5, float* __restrict__ out)
{
    extern __shared__ float sm[];
    const int tid = threadIdx.x;
    const int c = blockIdx.x & 7, g = blockIdx.x >> 3;

    uint32_t sb;
    asm("{ .reg .u64 t; cvta.to.shared.u64 t,%1; cvt.u32.u64 %0,t; }" : "=r"(sb) : "l"(sm));
    const uint32_t mRDY1 = sb, mRDY2 = sb + 8, mF2 = sb + 16;
    if (tid == 0) { mb_init(mRDY1, 8); mb_init(mRDY2, 8); mb_init(mF2, 8); }

    // ---- stage weights (col-blocked per k: [z|r|h]) ----
    for (int i = tid; i < 24576; i += NTHR) {
        int k = i / 96, j = i % 96;
        sm[OFF_R1 + i] = r1[k*768 + (j>>5)*256 + (c<<5) + (j&31)];
    }
    for (int i = tid; i < 12288; i += NTHR) {
        int k = i / 48, j = i % 48;
        sm[OFF_K2 + i] = k2[k*384 + (j>>4)*128 + (c<<4) + (j&15)];
    }
    for (int i = tid; i < 6144; i += NTHR) {
        int k = i / 48, j = i % 48;
        sm[OFF_R2 + i] = r2[k*384 + (j>>4)*128 + (c<<4) + (j&15)];
    }
    for (int i = tid; i < 2*Br*H1S; i += NTHR) sm[OFF_H1 + i] = 0.f;
    for (int i = tid; i < Br*H2S;   i += NTHR) sm[OFF_H2 + i] = 0.f;
    #pragma unroll
    for (int j = 0; j < 2; j++) {    // x(0)
        int i = tid*2 + j, r = i >> 4, f = i & 15;
        *(float4*)(sm + OFF_XS + r*XSS + f*4) =
            *(const float4*)(x + ((size_t)(g*Br + r)*T)*64 + f*4);
    }

    // ---- thread mappings ----
    const int kcA = tid >> 6, rgA = (tid >> 3) & 7, ctA = tid & 7, rA0 = rgA*2;
    const int kcB = tid >> 5, rgB = (tid >> 2) & 7, ctB = tid & 3, rB0 = rgB*2;

    // ---- biases ----
    ull bzA[2], brA[2], bxA[2], bhA[2];
    if (kcA == 0) {
        #pragma unroll
        for (int p = 0; p < 2; p++) {
            int u0 = (c<<5) + ctA*4 + p*2, u1 = u0 + 1;
            bzA[p] = pk2(b1[u0]+b1[768+u0],       b1[u1]+b1[768+u1]);
            brA[p] = pk2(b1[256+u0]+b1[1024+u0],  b1[256+u1]+b1[1024+u1]);
            bxA[p] = pk2(b1[512+u0],              b1[512+u1]);
            bhA[p] = pk2(b1[1280+u0],             b1[1280+u1]);
        }
    }
    ull bzB[2], brB[2], bxB[2], bhB[2];
    if (kcB == 0) {
        #pragma unroll
        for (int p = 0; p < 2; p++) {
            int u0 = (c<<4) + ctB*4 + p*2, u1 = u0 + 1;
            bzB[p] = pk2(b2[u0]+b2[384+u0],       b2[u1]+b2[384+u1]);
            brB[p] = pk2(b2[128+u0]+b2[512+u0],   b2[128+u1]+b2[512+u1]);
            bxB[p] = pk2(b2[256+u0],              b2[256+u1]);
            bhB[p] = pk2(b2[640+u0],              b2[640+u1]);
        }
    }

    uint32_t map1[CL], map2[CL];
    {
        uint32_t la1 = sb + (uint32_t)(OFF_H1 + rA0*H1S + (c<<5) + ctA*4)*4u;
        uint32_t la2 = sb + (uint32_t)(OFF_H2 + rB0*H2S + (c<<4) + ctB*4)*4u;
        #pragma unroll
        for (int rk = 0; rk < CL; rk++) { map1[rk] = mapa_u32(la1, rk); map2[rk] = mapa_u32(la2, rk); }
    }
    const ull2* R1p = (const ull2*)(sm + OFF_R1);
    const ull2* K2p = (const ull2*)(sm + OFF_K2);
    const ull2* R2p = (const ull2*)(sm + OFF_R2);
    const ull2* K1g = (const ull2*)k1;     // global k1, read per step (L2-resident)
    ull* scU = (ull*)(sm + OFF_SC);

    __syncthreads();
    cl_sync();

    for (int t = 0; t < T; t++) {
        const uint32_t par = (uint32_t)(t & 1);
        // x(t+1) -> regs
        float4 xr0, xr1;
        if (t + 1 < T) {
            int i0 = tid*2, r0 = i0>>4, f0 = i0&15;
            xr0 = *(const float4*)(x + ((size_t)(g*Br+r0)*T + t+1)*64 + f0*4);
            int i1 = i0+1, r1i = i1>>4, f1 = i1&15;
            xr1 = *(const float4*)(x + ((size_t)(g*Br+r1i)*T + t+1)*64 + f1*4);
        }

        // ---- GRU2 recurrent proj (reads h2(t-1)) ----
        if (t) mb_wait(mRDY2, (t-1)&1);
        ull bz[2][2], br_[2][2], bx[2][2], bh[2][2];
        #pragma unroll
        for (int rr = 0; rr < 2; rr++)
            #pragma unroll
            for (int p = 0; p < 2; p++) {
                bz[rr][p]  = (kcB == 0) ? bzB[p] : 0ull;
                br_[rr][p] = (kcB == 0) ? brB[p] : 0ull;
                bx[rr][p]  = (kcB == 0) ? bxB[p] : 0ull;
                bh[rr][p]  = (kcB == 0) ? bhB[p] : 0ull;
            }
        {
            const float* g0 = sm + OFF_H2 + rB0*H2S;
            const float* g1 = g0 + H2S;
            const int kb = kcB * 32;
            #pragma unroll 4
            for (int kk = 0; kk < 32; kk++) {
                int k = kb + kk;
                ull v0 = pk2(g0[k], g0[k]), v1 = pk2(g1[k], g1[k]);
                ull2 wz = R2p[k*12+ctB], wr = R2p[k*12+4+ctB], wh = R2p[k*12+8+ctB];
                f2(bz[0][0], v0, wz.x); f2(bz[0][1], v0, wz.y);
                f2(bz[1][0], v1, wz.x); f2(bz[1][1], v1, wz.y);
                f2(br_[0][0], v0, wr.x); f2(br_[0][1], v0, wr.y);
                f2(br_[1][0], v1, wr.x); f2(br_[1][1], v1, wr.y);
                f2(bh[0][0], v0, wh.x); f2(bh[0][1], v0, wh.y);
                f2(bh[1][0], v1, wh.x); f2(bh[1][1], v1, wh.y);
            }
        }
        __syncthreads();                       // A: all done reading h2(t-1)
        if (tid < 8) mb_post(mF2, (uint32_t)tid);

        // ---- GRU1 projections (read x(t), h1[(t-1)&1]) ----
        ull az[2][2], ar[2][2], ax[2][2], ah[2][2];
        #pragma unroll
        for (int rr = 0; rr < 2; rr++)
            #pragma unroll
            for (int p = 0; p < 2; p++) {
                az[rr][p] = (kcA == 0) ? bzA[p] : 0ull;
                ar[rr][p] = (kcA == 0) ? brA[p] : 0ull;
                ax[rr][p] = (kcA == 0) ? bxA[p] : 0ull;
                ah[rr][p] = (kcA == 0) ? bhA[p] : 0ull;
            }
        const float* h0 = sm + OFF_H1 + ((t+1)&1)*Br*H1S + rA0*H1S;   // buf (t-1)&1
        const float* h1r = h0 + H1S;
        if (kcA == 0) {   // x @ k1 (k1 from GLOBAL) ; h1 k in [0,64)
            const float* x0 = sm + OFF_XS + rA0*XSS;
            const float* x1 = x0 + XSS;
            #pragma unroll 4
            for (int k = 0; k < 64; k++) {
                ull v0 = pk2(x0[k], x0[k]), v1 = pk2(x1[k], x1[k]);
                int gi = k*192 + (c<<3) + ctA;
                ull2 wz = K1g[gi], wr = K1g[gi+64], wh = K1g[gi+128];
                f2(az[0][0], v0, wz.x); f2(az[0][1], v0, wz.y);
                f2(az[1][0], v1, wz.x); f2(az[1][1], v1, wz.y);
                f2(ar[0][0], v0, wr.x); f2(ar[0][1], v0, wr.y);
                f2(ar[1][0], v1, wr.x); f2(ar[1][1], v1, wr.y);
                f2(ax[0][0], v0, wh.x); f2(ax[0][1], v0, wh.y);
                f2(ax[1][0], v1, wh.x); f2(ax[1][1], v1, wh.y);
            }
        }
        {   // recurrent: kc0 k in [0,64), kc1 k in [64,256)
            const int kb = kcA ? 64 : 0, ke = kcA ? 256 : 64;
            #pragma unroll 4
            for (int k = kb; k < ke; k++) {
                ull v0 = pk2(h0[k], h0[k]), v1 = pk2(h1r[k], h1r[k]);
                ull2 wz = R1p[k*24+ctA], wr = R1p[k*24+8+ctA], wh = R1p[k*24+16+ctA];
                f2(az[0][0], v0, wz.x); f2(az[0][1], v0, wz.y);
                f2(az[1][0], v1, wz.x); f2(az[1][1], v1, wz.y);
                f2(ar[0][0], v0, wr.x); f2(ar[0][1], v0, wr.y);
                f2(ar[1][0], v1, wr.x); f2(ar[1][1], v1, wr.y);
                f2(ah[0][0], v0, wh.x); f2(ah[0][1], v0, wh.y);
                f2(ah[1][0], v1, wh.x); f2(ah[1][1], v1, wh.y);
            }
        }
        if (kcA == 1) {   // GRU1 partials: 12 ull per thread
            int s = (rgA*8 + ctA) * 12;
            #pragma unroll
            for (int rr = 0; rr < 2; rr++)
                #pragma unroll
                for (int p = 0; p < 2; p++) {
                    scU[s + rr*2 + p]     = az[rr][p];
                    scU[s + 4 + rr*2 + p] = ar[rr][p];
                    scU[s + 8 + rr*2 + p] = ah[rr][p];
                }
        }
        __syncthreads();                       // B
        if (t + 1 < T) {                       // STS x(t+1) (readers done at B)
            int i0 = tid*2, r0 = i0>>4, f0 = i0&15;
            *(float4*)(sm + OFF_XS + r0*XSS + f0*4) = xr0;
            int i1 = i0+1, r1i = i1>>4, f1 = i1&15;
            *(float4*)(sm + OFF_XS + r1i*XSS + f1*4) = xr1;
        }
        if (kcA == 0) {   // reduce + gates + publish h1(t) -> buf t&1 (no WAR wait!)
            float hn1[2][4];
            int s = (rgA*8 + ctA) * 12;
            #pragma unroll
            for (int rr = 0; rr < 2; rr++) {
                const float* hr = (rr == 0) ? h0 : h1r;
                #pragma unroll
                for (int p = 0; p < 2; p++) {
                    a2(az[rr][p], scU[s + rr*2 + p]);
                    a2(ar[rr][p], scU[s + 4 + rr*2 + p]);
                    a2(ah[rr][p], scU[s + 8 + rr*2 + p]);
                    float2 vz = upk(az[rr][p]), vr = upk(ar[rr][p]);
                    float2 vx = upk(ax[rr][p]), vh = upk(ah[rr][p]);
                    int col = (c<<5) + ctA*4 + p*2;
                    float z0 = sigf(vz.x), r0 = sigf(vr.x);
                    float hh0 = tanhf_(vx.x + r0*vh.x);
                    float z1 = sigf(vz.y), r1g = sigf(vr.y);
                    float hh1 = tanhf_(vx.y + r1g*vh.y);
                    hn1[rr][p*2]   = z0*hr[col]   + (1.f - z0)*hh0;
                    hn1[rr][p*2+1] = z1*hr[col+1] + (1.f - z1)*hh1;
                }
            }
            ull q00 = pk2(hn1[0][0], hn1[0][1]), q01 = pk2(hn1[0][2], hn1[0][3]);
            ull q10 = pk2(hn1[1][0], hn1[1][1]), q11 = pk2(hn1[1][2], hn1[1][3]);
            uint32_t bo = par * H1BUF_B;
            #pragma unroll
            for (int rk = 0; rk < CL; rk++) {
                uint32_t p0 = map1[rk] + bo;
                st_rem64(p0, q00); st_rem64(p0 + 8, q01);
                uint32_t p1 = p0 + (uint32_t)(H1S*4);
                st_rem64(p1, q10); st_rem64(p1 + 8, q11);
            }
        }
        __syncthreads();                       // D
        if (tid < 8) mb_post(mRDY1, (uint32_t)tid);
        mb_wait(mRDY1, par);                   // h1(t) visible

        // ---- GRU2 input proj (h1(t) @ k2) ----
        {
            const float* g0 = sm + OFF_H1 + par*Br*H1S + rB0*H1S;
            const float* g1 = g0 + H1S;
            const int kb = kcB * 64;
            #pragma unroll 4
            for (int kk = 0; kk < 64; kk++) {
                int k = kb + kk;
                ull v0 = pk2(g0[k], g0[k]), v1 = pk2(g1[k], g1[k]);
                ull2 wz = K2p[k*12+ctB], wr = K2p[k*12+4+ctB], wh = K2p[k*12+8+ctB];
                f2(bz[0][0], v0, wz.x); f2(bz[0][1], v0, wz.y);
                f2(bz[1][0], v1, wz.x); f2(bz[1][1], v1, wz.y);
                f2(br_[0][0], v0, wr.x); f2(br_[0][1], v0, wr.y);
                f2(br_[1][0], v1, wr.x); f2(br_[1][1], v1, wr.y);
                f2(bx[0][0], v0, wh.x); f2(bx[0][1], v0, wh.y);
                f2(bx[1][0], v1, wh.x); f2(bx[1][1], v1, wh.y);
            }
        }
        if (kcB > 0) {    // single-phase partials: 16 ull per thread
            int s = (kcB-1)*512 + (rgB*4 + ctB)*16;
            #pragma unroll
            for (int rr = 0; rr < 2; rr++)
                #pragma unroll
                for (int p = 0; p < 2; p++) {
                    scU[s +      rr*2 + p] = bz[rr][p];
                    scU[s + 4  + rr*2 + p] = br_[rr][p];
                    scU[s + 8  + rr*2 + p] = bx[rr][p];
                    scU[s + 12 + rr*2 + p] = bh[rr][p];
                }
        }
        __syncthreads();                       // E
        if (kcB == 0) {
            float hn2[2][4];
            #pragma unroll
            for (int m = 0; m < 3; m++) {
                int s = m*512 + (rgB*4 + ctB)*16;
                #pragma unroll
                for (int rr = 0; rr < 2; rr++)
                    #pragma unroll
                    for (int p = 0; p < 2; p++) {
                        a2(bz[rr][p],  scU[s +      rr*2 + p]);
                        a2(br_[rr][p], scU[s + 4  + rr*2 + p]);
                        a2(bx[rr][p],  scU[s + 8  + rr*2 + p]);
                        a2(bh[rr][p],  scU[s + 12 + rr*2 + p]);
                    }
            }
            #pragma unroll
            for (int rr = 0; rr < 2; rr++) {
                int r = rB0 + rr;
                #pragma unroll
                for (int p = 0; p < 2; p++) {
                    float2 vz = upk(bz[rr][p]), vr = upk(br_[rr][p]);
                    float2 vx = upk(bx[rr][p]), vh = upk(bh[rr][p]);
                    int col = (c<<4) + ctB*4 + p*2;
                    float hp0 = sm[OFF_H2 + r*H2S + col];
                    float hp1 = sm[OFF_H2 + r*H2S + col + 1];
                    float z0 = sigf(vz.x), r0 = sigf(vr.x);
                    float hh0 = tanhf_(vx.x + r0*vh.x);
                    float z1 = sigf(vz.y), r1g = sigf(vr.y);
                    float hh1 = tanhf_(vx.y + r1g*vh.y);
                    hn2[rr][p*2]   = z0*hp0 + (1.f - z0)*hh0;
                    hn2[rr][p*2+1] = z1*hp1 + (1.f - z1)*hh1;
                }
            }
            mb_wait(mF2, par);                 // all CTAs done reading h2(t-1)
            ull q00 = pk2(hn2[0][0], hn2[0][1]), q01 = pk2(hn2[0][2], hn2[0][3]);
            ull q10 = pk2(hn2[1][0], hn2[1][1]), q11 = pk2(hn2[1][2], hn2[1][3]);
            #pragma unroll
            for (int rk = 0; rk < CL; rk++) {
                uint32_t p0 = map2[rk];
                st_rem64(p0, q00); st_rem64(p0 + 8, q01);
                uint32_t p1 = p0 + (uint32_t)(H2S*4);
                st_rem64(p1, q10); st_rem64(p1 + 8, q11);
            }
        }
        __syncthreads();                       // I
        if (tid < 8) mb_post(mRDY2, (uint32_t)tid);
    }
    mb_wait(mRDY2, (uint32_t)((T-1)&1));       // final h2 delivered everywhere

    // ---- Dense head (rank 0 CTAs) ----
    if (c == 0) {
        float* sD3 = sm + OFF_XS;              // [16][64]
        float* sD4 = sm + OFF_SC;              // [16][32]
        __syncthreads();
        for (int i = tid; i < Br*64; i += NTHR) {
            int r = i >> 6, o = i & 63;
            float a = b3[o];
            #pragma unroll 8
            for (int k = 0; k < 128; k++) a += sm[OFF_H2 + r*H2S + k] * w3[k*64 + o];
            sD3[i] = a;
        }
        __syncthreads();
        for (int i = tid; i < Br*32; i += NTHR) {
            int r = i >> 5, o = i & 31;
            float a = b4[o];
            #pragma unroll 8
            for (int k = 0; k < 64; k++) a += sD3[r*64 + k] * w4[k*32 + o];
            sD4[i] = a;
        }
        __syncthreads();
        for (int i = tid; i < Br*OUTW; i += NTHR) {
            int r = i / OUTW, o = i % OUTW;
            float a = b5[o];
            #pragma unroll 8
            for (int k = 0; k < 32; k++) a += sD4[r*32 + k] * w5[k*OUTW + o];
            out[(g*Br + r)*OUTW + o] = a;
        }
    }
}

extern "C" void kernel_launch(void* const* d_in, const int* in_sizes, int n_in,
                              void* d_out, int out_size) {
    (void)in_sizes; (void)n_in; (void)out_size;
    const float* x  = (const float*)d_in[0];
    const float* k1 = (const float*)d_in[1];
    const float* r1 = (const float*)d_in[2];
    const float* b1 = (const float*)d_in[3];
    const float* k2 = (const float*)d_in[4];
    const float* r2 = (const float*)d_in[5];
    const float* b2 = (const float*)d_in[6];
    const float* w3 = (const float*)d_in[7];
    const float* b3 = (const float*)d_in[8];
    const float* w4 = (const float*)d_in[9];
    const float* b4 = (const float*)d_in[10];
    const float* w5 = (const float*)d_in[11];
    const float* b5 = (const float*)d_in[12];
    float* out = (float*)d_out;
    cudaFuncSetAttribute(gru_stack_kernel,
                         cudaFuncAttributeMaxDynamicSharedMemorySize, (int)SMEM_BYTES);
    gru_stack_kernel<<<128, NTHR, SMEM_BYTES>>>(
        x, k1, r1, b1, k2, r2, b2, w3, b3, w4, b4, w5, b5, out);
}

// round 12
// speedup vs baseline: 1.5999x; 1.2985x over previous
#include <cuda_runtime.h>
#include <cstdint>
#include <cstddef>
typedef unsigned long long ull; typedef ulonglong2 ull2;
#define DI __device__ __forceinline__

namespace {
constexpr int T = 512, OUTW = 24, CL = 8, Br = 16, NTHR = 128;
constexpr int H1S = 258, H2S = 130, XSS = 68;
constexpr int OFF_R1 = 8;
constexpr int OFF_K1 = OFF_R1 + 24576;
constexpr int OFF_K2 = OFF_K1 + 6144;
constexpr int OFF_R2 = OFF_K2 + 12288;
constexpr int OFF_H1 = OFF_R2 + 6144;
constexpr int OFF_H2 = OFF_H1 + Br * H1S;
constexpr int OFF_XS = OFF_H2 + Br * H2S;
constexpr int OFF_SC = OFF_XS + Br * XSS;
constexpr int SMEM_FLOATS = OFF_SC + 1632;
constexpr size_t SMEM_BYTES = SMEM_FLOATS * sizeof(float);  // 232352
}

DI float sigf(float v) { return __fdividef(1.f, 1.f + __expf(-v)); }
DI float tanhf_(float v) {
    float e = __expf(2.f * fabsf(v));
    return copysignf(1.f - __fdividef(2.f, e + 1.f), v);
}
DI void cl_sync() {
    asm volatile("barrier.cluster.arrive.aligned;" ::: "memory");
    asm volatile("barrier.cluster.wait.aligned;" ::: "memory");
}
DI uint32_t mapa_u32(uint32_t a, uint32_t r) {
    uint32_t p; asm("mapa.shared::cluster.u32 %0,%1,%2;" : "=r"(p) : "r"(a), "r"(r)); return p;
}
DI void st_rem64(uint32_t a, ull v) {
    asm volatile("st.shared::cluster.b64 [%0],%1;" :: "r"(a), "l"(v) : "memory");
}
DI ull pk2(float a, float b) { ull r; asm("mov.b64 %0,{%1,%2};" : "=l"(r) : "f"(a), "f"(b)); return r; }
DI float2 upk(ull v) { float2 r; asm("mov.b64 {%0,%1},%2;" : "=f"(r.x), "=f"(r.y) : "l"(v)); return r; }
DI void f2(ull& d, ull a, ull b) { asm("fma.rn.f32x2 %0,%1,%2,%0;" : "+l"(d) : "l"(a), "l"(b)); }
DI void a2(ull& d, ull b) { asm("add.rn.f32x2 %0,%0,%1;" : "+l"(d) : "l"(b)); }
DI void mb_init(uint32_t a, uint32_t n) {
    asm volatile("mbarrier.init.shared.b64 [%0],%1;" :: "r"(a), "r"(n) : "memory");
}
DI void mb_post(uint32_t la, uint32_t rk) {
    asm volatile("{ .reg .b32 ra;\n\t"
        "mapa.shared::cluster.u32 ra,%0,%1;\n\t"
        "mbarrier.arrive.release.cluster.shared::cluster.b64 _,[ra]; }"
        :: "r"(la), "r"(rk) : "memory");
}
DI void mb_wait(uint32_t a, uint32_t p) {
    asm volatile("{ .reg .pred P;\n"
        "W%=: mbarrier.try_wait.parity.acquire.cluster.shared::cta.b64 P,[%0],%1,0x989680;\n\t"
        "@P bra.uni D%=;\n\t"
        "bra.uni W%=;\n"
        "D%=: }" :: "r"(a), "r"(p) : "memory");
}

__global__ void __launch_bounds__(NTHR, 1) __cluster_dims__(CL, 1, 1)
gru_stack_kernel(const float* __restrict__ x,  const float* __restrict__ k1,
                 const float* __restrict__ r1, const float* __restrict__ b1,
                 const float* __restrict__ k2, const float* __restrict__ r2,
                 const float* __restrict__ b2, const float* __restrict__ w3,
                 const float* __restrict__ b3, const float* __restrict__ w4,
                 const float* __restrict__ b4, const float* __restrict__ w5,
                 const float* __restrict__ b5, float* __restrict__ out)
{
    extern __shared__ float sm[];
    const int tid = threadIdx.x;
    const int c = blockIdx.x & 7, g = blockIdx.x >> 3;

    uint32_t sb;
    asm("{ .reg .u64 t; cvta.to.shared.u64 t,%1; cvt.u32.u64 %0,t; }" : "=r"(sb) : "l"(sm));
    const uint32_t mFREE = sb, mRDY1 = sb + 8, mRDY2 = sb + 16;
    if (tid == 0) { mb_init(mFREE, 8); mb_init(mRDY1, 8); mb_init(mRDY2, 8); }

    for (int i = tid; i < 24576; i += NTHR) {
        int k = i / 96, j = i % 96;
        sm[OFF_R1 + i] = r1[k*768 + (j>>5)*256 + (c<<5) + (j&31)];
    }
    for (int i = tid; i < 6144; i += NTHR) {
        int k = i / 96, j = i % 96;
        sm[OFF_K1 + i] = k1[k*768 + (j>>5)*256 + (c<<5) + (j&31)];
    }
    for (int i = tid; i < 12288; i += NTHR) {
        int k = i / 48, j = i % 48;
        sm[OFF_K2 + i] = k2[k*384 + (j>>4)*128 + (c<<4) + (j&15)];
    }
    for (int i = tid; i < 6144; i += NTHR) {
        int k = i / 48, j = i % 48;
        sm[OFF_R2 + i] = r2[k*384 + (j>>4)*128 + (c<<4) + (j&15)];
    }
    for (int i = tid; i < Br*H1S; i += NTHR) sm[OFF_H1 + i] = 0.f;
    for (int i = tid; i < Br*H2S; i += NTHR) sm[OFF_H2 + i] = 0.f;
    for (int i = tid; i < Br*64; i += NTHR) {
        int r = i >> 6, f = i & 63;
        sm[OFF_XS + r*XSS + f] = x[((size_t)(g*Br + r)*T)*64 + f];
    }

    const int kcA = tid >> 6, rgA = (tid >> 3) & 7, ctA = tid & 7, rA0 = rgA*2;
    const int kcB = tid >> 5, rgB = (tid >> 2) & 7, ctB = tid & 3, rB0 = rgB*2;

    ull bzA[2], brA[2], bxA[2], bhA[2];
    if (kcA == 0) {
        #pragma unroll
        for (int p = 0; p < 2; p++) {
            int u0 = (c<<5) + ctA*4 + p*2, u1 = u0 + 1;
            bzA[p] = pk2(b1[u0]+b1[768+u0],      b1[u1]+b1[768+u1]);
            brA[p] = pk2(b1[256+u0]+b1[1024+u0], b1[256+u1]+b1[1024+u1]);
            bxA[p] = pk2(b1[512+u0],             b1[512+u1]);
            bhA[p] = pk2(b1[1280+u0],            b1[1280+u1]);
        }
    }
    ull bzB[2], brB[2], bxB[2], bhB[2];
    if (kcB == 0) {
        #pragma unroll
        for (int p = 0; p < 2; p++) {
            int u0 = (c<<4) + ctB*4 + p*2, u1 = u0 + 1;
            bzB[p] = pk2(b2[u0]+b2[384+u0],      b2[u1]+b2[384+u1]);
            brB[p] = pk2(b2[128+u0]+b2[512+u0],  b2[128+u1]+b2[512+u1]);
            bxB[p] = pk2(b2[256+u0],             b2[256+u1]);
            bhB[p] = pk2(b2[640+u0],             b2[640+u1]);
        }
    }

    uint32_t map1[CL], map2[CL];
    {
        uint32_t la1 = sb + (uint32_t)(OFF_H1 + rA0*H1S + (c<<5) + ctA*4)*4u;
        uint32_t la2 = sb + (uint32_t)(OFF_H2 + rB0*H2S + (c<<4) + ctB*4)*4u;
        #pragma unroll
        for (int rk = 0; rk < CL; rk++) { map1[rk] = mapa_u32(la1, rk); map2[rk] = mapa_u32(la2, rk); }
    }
    const ull2* R1p = (const ull2*)(sm + OFF_R1);
    const ull2* K1p = (const ull2*)(sm + OFF_K1);
    const ull2* K2p = (const ull2*)(sm + OFF_K2);
    const ull2* R2p = (const ull2*)(sm + OFF_R2);
    ull* scU = (ull*)(sm + OFF_SC);

    // persistent previous hidden states (owned cols) in registers
    float hpr[2][4] = {{0,0,0,0},{0,0,0,0}};   // kcA==0: 2 rows x 4 GRU1 units
    float hqr[2][4] = {{0,0,0,0},{0,0,0,0}};   // kcB==0: 2 rows x 4 GRU2 units

    __syncthreads();
    cl_sync();

    for (int t = 0; t < T; t++) {
        const uint32_t par = (uint32_t)(t & 1);
        float4 xr[4];
        if (kcA == 1 && t + 1 < T) {
            #pragma unroll
            for (int j = 0; j < 4; j++) {
                int i = (tid - 64)*4 + j, r = i >> 4, f4 = i & 15;
                xr[j] = *(const float4*)(x + ((size_t)(g*Br + r)*T + t + 1)*64 + f4*4);
            }
        }

        // ---- GRU1 projections ----
        ull az[2][2], ar[2][2], ax[2][2], ah[2][2];
        #pragma unroll
        for (int rr = 0; rr < 2; rr++)
            #pragma unroll
            for (int p = 0; p < 2; p++) {
                az[rr][p] = (kcA == 0) ? bzA[p] : 0ull;
                ar[rr][p] = (kcA == 0) ? brA[p] : 0ull;
                ax[rr][p] = (kcA == 0) ? bxA[p] : 0ull;
                ah[rr][p] = (kcA == 0) ? bhA[p] : 0ull;
            }
        const float* h0 = sm + OFF_H1 + rA0*H1S;
        const float* h1r = h0 + H1S;
        if (kcA == 0) {
            const float* x0 = sm + OFF_XS + rA0*XSS;
            const float* x1 = x0 + XSS;
            #pragma unroll 4
            for (int k = 0; k < 64; k += 2) {
                float2 a0 = *(const float2*)(x0 + k);
                float2 a1 = *(const float2*)(x1 + k);
                #pragma unroll
                for (int s = 0; s < 2; s++) {
                    ull v0 = pk2(s ? a0.y : a0.x, s ? a0.y : a0.x);
                    ull v1 = pk2(s ? a1.y : a1.x, s ? a1.y : a1.x);
                    int kk = k + s;
                    ull2 wz = K1p[kk*24+ctA], wr = K1p[kk*24+8+ctA], wh = K1p[kk*24+16+ctA];
                    f2(az[0][0], v0, wz.x); f2(az[0][1], v0, wz.y);
                    f2(az[1][0], v1, wz.x); f2(az[1][1], v1, wz.y);
                    f2(ar[0][0], v0, wr.x); f2(ar[0][1], v0, wr.y);
                    f2(ar[1][0], v1, wr.x); f2(ar[1][1], v1, wr.y);
                    f2(ax[0][0], v0, wh.x); f2(ax[0][1], v0, wh.y);
                    f2(ax[1][0], v1, wh.x); f2(ax[1][1], v1, wh.y);
                }
            }
        }
        {
            const int kb = kcA ? 96 : 0, ke = kcA ? 256 : 96;
            #pragma unroll 4
            for (int k = kb; k < ke; k += 2) {
                float2 a0 = *(const float2*)(h0 + k);
                float2 a1 = *(const float2*)(h1r + k);
                #pragma unroll
                for (int s = 0; s < 2; s++) {
                    ull v0 = pk2(s ? a0.y : a0.x, s ? a0.y : a0.x);
                    ull v1 = pk2(s ? a1.y : a1.x, s ? a1.y : a1.x);
                    int kk = k + s;
                    ull2 wz = R1p[kk*24+ctA], wr = R1p[kk*24+8+ctA], wh = R1p[kk*24+16+ctA];
                    f2(az[0][0], v0, wz.x); f2(az[0][1], v0, wz.y);
                    f2(az[1][0], v1, wz.x); f2(az[1][1], v1, wz.y);
                    f2(ar[0][0], v0, wr.x); f2(ar[0][1], v0, wr.y);
                    f2(ar[1][0], v1, wr.x); f2(ar[1][1], v1, wr.y);
                    f2(ah[0][0], v0, wh.x); f2(ah[0][1], v0, wh.y);
                    f2(ah[1][0], v1, wh.x); f2(ah[1][1], v1, wh.y);
                }
            }
        }

        // ---- GRU2 recurrent proj (reads h2(t-1)) ----
        if (t > 0) mb_wait(mRDY2, (uint32_t)((t - 1) & 1));
        ull bz[2][2], br_[2][2], bx[2][2], bh[2][2];
        #pragma unroll
        for (int rr = 0; rr < 2; rr++)
            #pragma unroll
            for (int p = 0; p < 2; p++) {
                bz[rr][p]  = (kcB == 0) ? bzB[p] : 0ull;
                br_[rr][p] = (kcB == 0) ? brB[p] : 0ull;
                bx[rr][p]  = (kcB == 0) ? bxB[p] : 0ull;
                bh[rr][p]  = (kcB == 0) ? bhB[p] : 0ull;
            }
        {
            const float* g0 = sm + OFF_H2 + rB0*H2S;
            const float* g1 = g0 + H2S;
            const int kb = kcB * 32;
            #pragma unroll 4
            for (int k = kb; k < kb + 32; k += 2) {
                float2 a0 = *(const float2*)(g0 + k);
                float2 a1 = *(const float2*)(g1 + k);
                #pragma unroll
                for (int s = 0; s < 2; s++) {
                    ull v0 = pk2(s ? a0.y : a0.x, s ? a0.y : a0.x);
                    ull v1 = pk2(s ? a1.y : a1.x, s ? a1.y : a1.x);
                    int kk = k + s;
                    ull2 wz = R2p[kk*12+ctB], wr = R2p[kk*12+4+ctB], wh = R2p[kk*12+8+ctB];
                    f2(bz[0][0], v0, wz.x); f2(bz[0][1], v0, wz.y);
                    f2(bz[1][0], v1, wz.x); f2(bz[1][1], v1, wz.y);
                    f2(br_[0][0], v0, wr.x); f2(br_[0][1], v0, wr.y);
                    f2(br_[1][0], v1, wr.x); f2(br_[1][1], v1, wr.y);
                    f2(bh[0][0], v0, wh.x); f2(bh[0][1], v0, wh.y);
                    f2(bh[1][0], v1, wh.x); f2(bh[1][1], v1, wh.y);
                }
            }
        }
        __syncthreads();                       // S1
        if (tid < 8) mb_post(mFREE, (uint32_t)tid);

        if (kcA == 1) {
            #pragma unroll
            for (int rr = 0; rr < 2; rr++) {
                int r = rA0 + rr;
                #pragma unroll
                for (int p = 0; p < 2; p++) {
                    scU[r*50 +      ctA*2 + p] = az[rr][p];
                    scU[r*50 + 16 + ctA*2 + p] = ar[rr][p];
                    scU[r*50 + 32 + ctA*2 + p] = ah[rr][p];
                }
            }
            if (t + 1 < T) {
                #pragma unroll
                for (int j = 0; j < 4; j++) {
                    int i = (tid - 64)*4 + j, r = i >> 4, f4 = i & 15;
                    *(float4*)(sm + OFF_XS + r*XSS + f4*4) = xr[j];
                }
            }
        }
        __syncthreads();                       // S2
        if (kcA == 0) {
            float hn1[2][4];
            #pragma unroll
            for (int rr = 0; rr < 2; rr++) {
                int r = rA0 + rr;
                #pragma unroll
                for (int p = 0; p < 2; p++) {
                    a2(az[rr][p], scU[r*50 +      ctA*2 + p]);
                    a2(ar[rr][p], scU[r*50 + 16 + ctA*2 + p]);
                    a2(ah[rr][p], scU[r*50 + 32 + ctA*2 + p]);
                    float2 vz = upk(az[rr][p]), vr = upk(ar[rr][p]);
                    float2 vx = upk(ax[rr][p]), vh = upk(ah[rr][p]);
                    float z0 = sigf(vz.x), r0 = sigf(vr.x);
                    float hh0 = tanhf_(vx.x + r0*vh.x);
                    float z1 = sigf(vz.y), r1g = sigf(vr.y);
                    float hh1 = tanhf_(vx.y + r1g*vh.y);
                    hn1[rr][p*2]   = z0*hpr[rr][p*2]   + (1.f - z0)*hh0;
                    hn1[rr][p*2+1] = z1*hpr[rr][p*2+1] + (1.f - z1)*hh1;
                }
            }
            #pragma unroll
            for (int rr = 0; rr < 2; rr++)
                #pragma unroll
                for (int i = 0; i < 4; i++) hpr[rr][i] = hn1[rr][i];
            mb_wait(mFREE, par);
            ull q00 = pk2(hn1[0][0], hn1[0][1]), q01 = pk2(hn1[0][2], hn1[0][3]);
            ull q10 = pk2(hn1[1][0], hn1[1][1]), q11 = pk2(hn1[1][2], hn1[1][3]);
            #pragma unroll
            for (int rk = 0; rk < CL; rk++) {
                uint32_t p0 = map1[rk];
                st_rem64(p0, q00); st_rem64(p0 + 8, q01);
                uint32_t p1 = p0 + (uint32_t)(H1S*4);
                st_rem64(p1, q10); st_rem64(p1 + 8, q11);
            }
            asm volatile("bar.sync 1,64;" ::: "memory");
            if (tid < 8) mb_post(mRDY1, (uint32_t)tid);
        }
        mb_wait(mRDY1, par);                   // h1(t) visible

        // ---- GRU2 input proj (h1(t) @ k2) ----
        {
            const float* g0 = sm + OFF_H1 + rB0*H1S;
            const float* g1 = g0 + H1S;
            const int kb = kcB * 64;
            #pragma unroll 4
            for (int k = kb; k < kb + 64; k += 2) {
                float2 a0 = *(const float2*)(g0 + k);
                float2 a1 = *(const float2*)(g1 + k);
                #pragma unroll
                for (int s = 0; s < 2; s++) {
                    ull v0 = pk2(s ? a0.y : a0.x, s ? a0.y : a0.x);
                    ull v1 = pk2(s ? a1.y : a1.x, s ? a1.y : a1.x);
                    int kk = k + s;
                    ull2 wz = K2p[kk*12+ctB], wr = K2p[kk*12+4+ctB], wh = K2p[kk*12+8+ctB];
                    f2(bz[0][0], v0, wz.x); f2(bz[0][1], v0, wz.y);
                    f2(bz[1][0], v1, wz.x); f2(bz[1][1], v1, wz.y);
                    f2(br_[0][0], v0, wr.x); f2(br_[0][1], v0, wr.y);
                    f2(br_[1][0], v1, wr.x); f2(br_[1][1], v1, wr.y);
                    f2(bx[0][0], v0, wh.x); f2(bx[0][1], v0, wh.y);
                    f2(bx[1][0], v1, wh.x); f2(bx[1][1], v1, wh.y);
                }
            }
        }
        __syncthreads();                       // S3
        if (kcB > 0) {                         // phase 1: z, r
            int m = kcB - 1;
            #pragma unroll
            for (int rr = 0; rr < 2; rr++) {
                int r = rB0 + rr;
                #pragma unroll
                for (int p = 0; p < 2; p++) {
                    scU[m*272 + r*17 +     ctB*2 + p] = bz[rr][p];
                    scU[m*272 + r*17 + 8 + ctB*2 + p] = br_[rr][p];
                }
            }
        }
        __syncthreads();                       // S4
        if (kcB == 0) {
            #pragma unroll
            for (int m = 0; m < 3; m++)
                #pragma unroll
                for (int rr = 0; rr < 2; rr++) {
                    int r = rB0 + rr;
                    #pragma unroll
                    for (int p = 0; p < 2; p++) {
                        a2(bz[rr][p],  scU[m*272 + r*17 +     ctB*2 + p]);
                        a2(br_[rr][p], scU[m*272 + r*17 + 8 + ctB*2 + p]);
                    }
                }
        }
        __syncthreads();                       // S5
        if (kcB > 0) {                         // phase 2: hx, hh
            int m = kcB - 1;
            #pragma unroll
            for (int rr = 0; rr < 2; rr++) {
                int r = rB0 + rr;
                #pragma unroll
                for (int p = 0; p < 2; p++) {
                    scU[m*272 + r*17 +     ctB*2 + p] = bx[rr][p];
                    scU[m*272 + r*17 + 8 + ctB*2 + p] = bh[rr][p];
                }
            }
        }
        __syncthreads();                       // S6
        if (kcB == 0) {
            float hn2[2][4];
            #pragma unroll
            for (int rr = 0; rr < 2; rr++) {
                int r = rB0 + rr;
                #pragma unroll
                for (int p = 0; p < 2; p++) {
                    #pragma unroll
                    for (int m = 0; m < 3; m++) {
                        a2(bx[rr][p], scU[m*272 + r*17 +     ctB*2 + p]);
                        a2(bh[rr][p], scU[m*272 + r*17 + 8 + ctB*2 + p]);
                    }
                    float2 vz = upk(bz[rr][p]), vr = upk(br_[rr][p]);
                    float2 vx = upk(bx[rr][p]), vh = upk(bh[rr][p]);
                    float z0 = sigf(vz.x), r0 = sigf(vr.x);
                    float hh0 = tanhf_(vx.x + r0*vh.x);
                    float z1 = sigf(vz.y), r1g = sigf(vr.y);
                    float hh1 = tanhf_(vx.y + r1g*vh.y);
                    hn2[rr][p*2]   = z0*hqr[rr][p*2]   + (1.f - z0)*hh0;
                    hn2[rr][p*2+1] = z1*hqr[rr][p*2+1] + (1.f - z1)*hh1;
                }
            }
            #pragma unroll
            for (int rr = 0; rr < 2; rr++)
                #pragma unroll
                for (int i = 0; i < 4; i++) hqr[rr][i] = hn2[rr][i];
            mb_wait(mFREE, par);               // already complete; acquire only
            ull q00 = pk2(hn2[0][0], hn2[0][1]), q01 = pk2(hn2[0][2], hn2[0][3]);
            ull q10 = pk2(hn2[1][0], hn2[1][1]), q11 = pk2(hn2[1][2], hn2[1][3]);
            #pragma unroll
            for (int rk = 0; rk < CL; rk++) {
                uint32_t p0 = map2[rk];
                st_rem64(p0, q00); st_rem64(p0 + 8, q01);
                uint32_t p1 = p0 + (uint32_t)(H2S*4);
                st_rem64(p1, q10); st_rem64(p1 + 8, q11);
            }
            __syncwarp();
            if (tid < 8) mb_post(mRDY2, (uint32_t)tid);
        }
    }
    mb_wait(mRDY2, (uint32_t)((T - 1) & 1));

    if (c == 0) {
        float* sD3 = sm + OFF_SC;
        float* sD4 = sm + OFF_SC + Br*64;
        __syncthreads();
        for (int i = tid; i < Br*64; i += NTHR) {
            int r = i >> 6, o = i & 63;
            float a = b3[o];
            #pragma unroll 8
            for (int k = 0; k < 128; k++) a += sm[OFF_H2 + r*H2S + k] * w3[k*64 + o];
            sD3[i] = a;
        }
        __syncthreads();
        for (int i = tid; i < Br*32; i += NTHR) {
            int r = i >> 5, o = i & 31;
            float a = b4[o];
            #pragma unroll 8
            for (int k = 0; k < 64; k++) a += sD3[r*64 + k] * w4[k*32 + o];
            sD4[i] = a;
        }
        __syncthreads();
        for (int i = tid; i < Br*OUTW; i += NTHR) {
            int r = i / OUTW, o = i % OUTW;
            float a = b5[o];
            #pragma unroll 8
            for (int k = 0; k < 32; k++) a += sD4[r*32 + k] * w5[k*OUTW + o];
            out[(g*Br + r)*OUTW + o] = a;
        }
    }
}

extern "C" void kernel_launch(void* const* d_in, const int* in_sizes, int n_in,
                              void* d_out, int out_size) {
    (void)in_sizes; (void)n_in; (void)out_size;
    const float* x  = (const float*)d_in[0];
    const float* k1 = (const float*)d_in[1];
    const float* r1 = (const float*)d_in[2];
    const float* b1 = (const float*)d_in[3];
    const float* k2 = (const float*)d_in[4];
    const float* r2 = (const float*)d_in[5];
    const float* b2 = (const float*)d_in[6];
    const float* w3 = (const float*)d_in[7];
    const float* b3 = (const float*)d_in[8];
    const float* w4 = (const float*)d_in[9];
    const float* b4 = (const float*)d_in[10];
    const float* w5 = (const float*)d_in[11];
    const float* b5 = (const float*)d_in[12];
    float* out = (float*)d_out;
    cudaFuncSetAttribute(gru_stack_kernel,
                         cudaFuncAttributeMaxDynamicSharedMemorySize, (int)SMEM_BYTES);
    gru_stack_kernel<<<128, NTHR, SMEM_BYTES>>>(
        x, k1, r1, b1, k2, r2, b2, w3, b3, w4, b4, w5, b5, out);
}